// round 11
// baseline (speedup 1.0000x reference)
#include <cuda_runtime.h>
#include <cuda_fp16.h>
#include <cstdint>
#include <type_traits>

// ---------------------------------------------------------------------------
// LocalAttention: x(2,2048,1024) -> qkv gemm -> 27-neighbor local attention
//                 (8x16x16 grid, 16 heads x 64 dim) -> out-proj gemm.
// Round 11: 16-warp GEMM thesis (4 warps/SMSP, 64x32 warp tiles) mounted on
//           the round-7 proven 4-stage/per-chunk-sync pipeline (122.9 KB smem)
//           after the round-9/10 variant failed at the container level twice.
//           Attention unchanged from round 8.
// ---------------------------------------------------------------------------

#define TOKEN_T  8
#define TOKEN_HH 16
#define TOKEN_WW 16
#define NTOK     2048
#define BATCH    2
#define HID      1024
#define NHEAD    16
#define HDIM     64
#define M_TOT    (BATCH * NTOK)   // 4096

// Scratch (device globals: allocation-free per harness rules)
__device__ __half g_qkvh[(size_t)M_TOT * 3 * HID];
__device__ __half g_xh[(size_t)M_TOT * HID];
__device__ __half g_wqh[(size_t)3 * HID * HID];
__device__ __half g_woh[(size_t)HID * HID];
__device__ __half g_atth[(size_t)M_TOT * HID];

// ---------------------------------------------------------------------------
// Fused fp32 -> fp16 conversion of x, w_qkv, w_out in one launch.
// ---------------------------------------------------------------------------
#define X4  (M_TOT * HID / 4)
#define WQ4 (3 * HID * HID / 4)
#define WO4 (HID * HID / 4)

__global__ void cvt_all(const float4* __restrict__ x,
                        const float4* __restrict__ wq,
                        const float4* __restrict__ wo,
                        uint2* __restrict__ xh,
                        uint2* __restrict__ wqh,
                        uint2* __restrict__ woh) {
    int i = blockIdx.x * blockDim.x + threadIdx.x;
    const float4* src;
    uint2* dst;
    int j;
    if (i < X4)                  { src = x;  dst = xh;  j = i; }
    else if (i < X4 + WQ4)       { src = wq; dst = wqh; j = i - X4; }
    else if (i < X4 + WQ4 + WO4) { src = wo; dst = woh; j = i - X4 - WQ4; }
    else return;
    float4 v = src[j];
    __half2 a = __floats2half2_rn(v.x, v.y);
    __half2 b = __floats2half2_rn(v.z, v.w);
    uint2 o;
    o.x = *reinterpret_cast<uint32_t*>(&a);
    o.y = *reinterpret_cast<uint32_t*>(&b);
    dst[j] = o;
}

// ---------------------------------------------------------------------------
// mma.sync helpers
// ---------------------------------------------------------------------------
__device__ __forceinline__ void ldsm4(uint32_t* r, uint32_t addr) {
    asm volatile("ldmatrix.sync.aligned.m8n8.x4.shared.b16 {%0,%1,%2,%3},[%4];\n"
                 : "=r"(r[0]), "=r"(r[1]), "=r"(r[2]), "=r"(r[3]) : "r"(addr));
}
__device__ __forceinline__ void mma16816(float* d, const uint32_t* a, const uint32_t* b) {
    asm volatile("mma.sync.aligned.m16n8k16.row.col.f32.f16.f16.f32 "
                 "{%0,%1,%2,%3},{%4,%5,%6,%7},{%8,%9},{%0,%1,%2,%3};\n"
                 : "+f"(d[0]), "+f"(d[1]), "+f"(d[2]), "+f"(d[3])
                 : "r"(a[0]), "r"(a[1]), "r"(a[2]), "r"(a[3]),
                   "r"(b[0]), "r"(b[1]));
}
__device__ __forceinline__ void cp_async8(uint32_t saddr, const void* gaddr) {
    asm volatile("cp.async.ca.shared.global [%0], [%1], 8;\n"
                 :: "r"(saddr), "l"(gaddr) : "memory");
}

// smem: per stage A(256 rows) | B(128 rows), 40 halves/row (80B, conflict-free)
#define GROW_B   80
#define AMAT_B   (256 * GROW_B)          // 20480 B
#define BMAT_B   (128 * GROW_B)          // 10240 B
#define GSTAGE_B (AMAT_B + BMAT_B)       // 30720 B
#define GSTAGES  4
#define GSMEM_B  (GSTAGES * GSTAGE_B)    // 122880 B

// ---------------------------------------------------------------------------
// fp16 tensor-core GEMM (NT): C[M,N] = A[M,K] * B[N,K]^T, fp32 accumulate.
// Block tile 256x128, BK=32, 16 warps (warp grid 4Mx4N, 64x32 warp tiles),
// 4-stage cp.async ring, per-chunk wait+barrier (prefetch distance 2).
// Hazard check: writes at iter c target stage (c+2)%4; live readers are at
// stages c%4 (this iter) and (c-1)%4 (slow warps) — differences 2 and 3 mod 4,
// disjoint. wait_group 2 retires group c before the barrier that releases
// compute on stage c. Requires M%256==0, N%128==0, K%32==0.
// ---------------------------------------------------------------------------
template <typename OutT>
__global__ __launch_bounds__(512, 1)
void gemm_f16_pipe(const __half* __restrict__ A, const __half* __restrict__ B,
                   OutT* __restrict__ C, int M, int N, int K) {
    extern __shared__ __align__(16) char smem_raw[];
    const uint32_t sb = (uint32_t)__cvta_generic_to_shared(smem_raw);

    const int tid  = threadIdx.x;
    const int lane = tid & 31;
    const int warp = tid >> 5;            // 0..15
    const int wm = (warp & 3) * 64;       // 4 warps down M
    const int wn = (warp >> 2) * 32;      // 4 warps across N
    const int mrow0 = blockIdx.y * 256;
    const int ncol0 = blockIdx.x * 128;

    float acc[4][4][4];
#pragma unroll
    for (int mi = 0; mi < 4; mi++)
#pragma unroll
        for (int ni = 0; ni < 4; ni++)
#pragma unroll
            for (int r = 0; r < 4; r++) acc[mi][ni][r] = 0.0f;

    const __half* pA = A + (size_t)mrow0 * K;
    const __half* pB = B + (size_t)ncol0 * K;

    // loader (512 threads): A = 2048 8B-chunks (4/thread), B = 1024 (2/thread)
    const int l_row = tid >> 3;          // 0..63
    const int l_c   = tid & 7;
    const uint32_t l_soff = (uint32_t)(l_row * GROW_B + l_c * 8);
    const size_t   l_goff = (size_t)l_row * K + l_c * 4;

    auto load_stage = [&](int buf, int k0) {
        const uint32_t stage = sb + buf * GSTAGE_B;
#pragma unroll
        for (int it = 0; it < 4; it++)
            cp_async8(stage + l_soff + (uint32_t)(it * 64 * GROW_B),
                      pA + l_goff + (size_t)(it * 64) * K + k0);
#pragma unroll
        for (int it = 0; it < 2; it++)
            cp_async8(stage + AMAT_B + l_soff + (uint32_t)(it * 64 * GROW_B),
                      pB + l_goff + (size_t)(it * 64) * K + k0);
        asm volatile("cp.async.commit_group;\n" ::: "memory");
    };

    // ldmatrix lane geometry
    const int a_row = (lane & 15);
    const int a_kof = (lane >> 4) << 3;
    const int b_loc = ((lane >> 3) & 1) * 8 + (lane & 7);
    const int b_kof = (lane >> 4) << 3;
    uint32_t aoff[4], boff[2];
#pragma unroll
    for (int mi = 0; mi < 4; mi++)
        aoff[mi] = (uint32_t)((wm + mi * 16 + a_row) * GROW_B + a_kof * 2);
#pragma unroll
    for (int p = 0; p < 2; p++)
        boff[p] = (uint32_t)(AMAT_B + (wn + p * 16 + b_loc) * GROW_B + b_kof * 2);

    const int nchunk = K / 32;                 // 32 for K=1024
    load_stage(0, 0);
    load_stage(1, 32);

    for (int c = 0; c < nchunk; c++) {
        if (c + 2 < nchunk) {
            load_stage((c + 2) & 3, (c + 2) * 32);
            asm volatile("cp.async.wait_group 2;\n" ::: "memory");
        } else if (c + 1 < nchunk) {
            asm volatile("cp.async.wait_group 1;\n" ::: "memory");
        } else {
            asm volatile("cp.async.wait_group 0;\n" ::: "memory");
        }
        __syncthreads();

        const uint32_t stage = sb + (c & 3) * GSTAGE_B;
#pragma unroll
        for (int kk = 0; kk < 2; kk++) {
            const uint32_t ko = (uint32_t)(kk * 32);
            uint32_t a[4][4];
            uint32_t b[4][2];
#pragma unroll
            for (int mi = 0; mi < 4; mi++)
                ldsm4(a[mi], stage + aoff[mi] + ko);
#pragma unroll
            for (int p = 0; p < 2; p++) {
                uint32_t r[4];
                ldsm4(r, stage + boff[p] + ko);
                b[p * 2 + 0][0] = r[0]; b[p * 2 + 0][1] = r[2];
                b[p * 2 + 1][0] = r[1]; b[p * 2 + 1][1] = r[3];
            }
#pragma unroll
            for (int mi = 0; mi < 4; mi++)
#pragma unroll
                for (int ni = 0; ni < 4; ni++)
                    mma16816(acc[mi][ni], a[mi], b[ni]);
        }
    }

    const int em = mrow0 + wm + (lane >> 2);
    const int en = ncol0 + wn + (lane & 3) * 2;
#pragma unroll
    for (int mi = 0; mi < 4; mi++) {
#pragma unroll
        for (int ni = 0; ni < 4; ni++) {
            if constexpr (std::is_same<OutT, __half>::value) {
                __half* c0 = C + (size_t)(em + mi * 16) * N + en + ni * 8;
                __half* c1 = C + (size_t)(em + mi * 16 + 8) * N + en + ni * 8;
                *reinterpret_cast<__half2*>(c0) = __floats2half2_rn(acc[mi][ni][0], acc[mi][ni][1]);
                *reinterpret_cast<__half2*>(c1) = __floats2half2_rn(acc[mi][ni][2], acc[mi][ni][3]);
            } else {
                float* c0 = C + (size_t)(em + mi * 16) * N + en + ni * 8;
                float* c1 = C + (size_t)(em + mi * 16 + 8) * N + en + ni * 8;
                *reinterpret_cast<float2*>(c0) = make_float2(acc[mi][ni][0], acc[mi][ni][1]);
                *reinterpret_cast<float2*>(c1) = make_float2(acc[mi][ni][2], acc[mi][ni][3]);
            }
        }
    }
}

// ---------------------------------------------------------------------------
// Smem-tiled local attention, fp16 in/out, fp32 math (round-8 version).
// OOB halo rows are zero -> logit exactly 0 in softmax + value 0, matching
// the reference's zero-padding.
// ---------------------------------------------------------------------------
#define AT_HALO 216
#define KSTRH   68
#define AT_SMEM ((2 * AT_HALO * KSTRH + 64 * 64) * 2)

__global__ __launch_bounds__(256, 3)
void local_attn_f16(const __half* __restrict__ qkv, __half* __restrict__ att) {
    extern __shared__ __align__(16) __half smh[];
    __half* k_s = smh;
    __half* v_s = smh + AT_HALO * KSTRH;
    __half* q_s = v_s + AT_HALO * KSTRH;

    const int tile = blockIdx.x;
    const int head = blockIdx.y;
    const int b    = blockIdx.z;
    const int t0 = (tile >> 4) * 4;
    const int h0 = ((tile >> 2) & 3) * 4;
    const int w0 = (tile & 3) * 4;
    const int tid = threadIdx.x;

    for (int idx = tid; idx < AT_HALO * 16; idx += 256) {
        const int tok = idx >> 4;
        const int c8  = idx & 15;
        const int ht = tok / 36, hh = (tok / 6) % 6, hw = tok % 6;
        const int gt = t0 - 1 + ht, gh = h0 - 1 + hh, gw = w0 - 1 + hw;
        uint2 kv = make_uint2(0u, 0u), vv = make_uint2(0u, 0u);
        if (gt >= 0 && gt < TOKEN_T && gh >= 0 && gh < TOKEN_HH &&
            gw >= 0 && gw < TOKEN_WW) {
            const int n = (gt * TOKEN_HH + gh) * TOKEN_WW + gw;
            const __half* base = qkv + ((size_t)(b * NTOK + n)) * (3 * HID) + head * HDIM + c8 * 4;
            kv = *reinterpret_cast<const uint2*>(base + HID);
            vv = *reinterpret_cast<const uint2*>(base + 2 * HID);
        }
        *reinterpret_cast<uint2*>(&k_s[tok * KSTRH + c8 * 4]) = kv;
        *reinterpret_cast<uint2*>(&v_s[tok * KSTRH + c8 * 4]) = vv;
    }
    for (int idx = tid; idx < 64 * 16; idx += 256) {
        const int tok = idx >> 4, c8 = idx & 15;
        const int lt = tok >> 4, lh = (tok >> 2) & 3, lw = tok & 3;
        const int n = ((t0 + lt) * TOKEN_HH + (h0 + lh)) * TOKEN_WW + (w0 + lw);
        uint2 qv = *reinterpret_cast<const uint2*>(
            qkv + ((size_t)(b * NTOK + n)) * (3 * HID) + head * HDIM + c8 * 4);
        *reinterpret_cast<uint2*>(&q_s[tok * 64 + c8 * 4]) = qv;
    }
    __syncthreads();

    const int warp = tid >> 5, lane = tid & 31;
    const int doff = (lane < 27)
        ? (lane / 9) * 36 + ((lane / 3) % 3) * 6 + (lane % 3) : 0;

#pragma unroll
    for (int i = 0; i < 8; i++) {
        const int tok = warp * 8 + i;
        const int lt = tok >> 4, lh = (tok >> 2) & 3, lw = tok & 3;
        const int base = (lt * 6 + lh) * 6 + lw;

        float s = 0.f;
        if (lane < 27) {
            const int hrow = base + doff;
            const __half2* kp = reinterpret_cast<const __half2*>(&k_s[hrow * KSTRH]);
            const __half2* qp = reinterpret_cast<const __half2*>(&q_s[tok * 64]);
            float s0 = 0.f, s1 = 0.f, s2 = 0.f, s3 = 0.f;
#pragma unroll
            for (int d = 0; d < 32; d += 4) {
                const float2 k0 = __half22float2(kp[d + 0]);
                const float2 q0 = __half22float2(qp[d + 0]);
                const float2 k1 = __half22float2(kp[d + 1]);
                const float2 q1 = __half22float2(qp[d + 1]);
                const float2 k2 = __half22float2(kp[d + 2]);
                const float2 q2 = __half22float2(qp[d + 2]);
                const float2 k3 = __half22float2(kp[d + 3]);
                const float2 q3 = __half22float2(qp[d + 3]);
                s0 = fmaf(q0.x, k0.x, s0); s0 = fmaf(q0.y, k0.y, s0);
                s1 = fmaf(q1.x, k1.x, s1); s1 = fmaf(q1.y, k1.y, s1);
                s2 = fmaf(q2.x, k2.x, s2); s2 = fmaf(q2.y, k2.y, s2);
                s3 = fmaf(q3.x, k3.x, s3); s3 = fmaf(q3.y, k3.y, s3);
            }
            s = ((s0 + s1) + (s2 + s3)) * 0.125f;
        }
        float sl = (lane < 27) ? s : -1e30f;
#pragma unroll
        for (int off = 16; off; off >>= 1)
            sl = fmaxf(sl, __shfl_xor_sync(0xffffffffu, sl, off));
        const float e = (lane < 27) ? __expf(s - sl) : 0.f;
        float den = e;
#pragma unroll
        for (int off = 16; off; off >>= 1)
            den += __shfl_xor_sync(0xffffffffu, den, off);
        const float w = e / den;

        float o0 = 0.f, o1 = 0.f;
#pragma unroll
        for (int j = 0; j < 27; j++) {
            const int rj = base + (j / 9) * 36 + ((j / 3) % 3) * 6 + (j % 3);
            const float wj = __shfl_sync(0xffffffffu, w, j);
            o0 = fmaf(wj, __half2float(v_s[rj * KSTRH + lane]), o0);
            o1 = fmaf(wj, __half2float(v_s[rj * KSTRH + lane + 32]), o1);
        }
        const int n = ((t0 + lt) * TOKEN_HH + (h0 + lh)) * TOKEN_WW + (w0 + lw);
        __half* op = att + ((size_t)(b * NTOK + n)) * HID + head * HDIM;
        op[lane]      = __float2half_rn(o0);
        op[lane + 32] = __float2half_rn(o1);
    }
}

// ---------------------------------------------------------------------------
// Launch
// ---------------------------------------------------------------------------
extern "C" void kernel_launch(void* const* d_in, const int* in_sizes, int n_in,
                              void* d_out, int out_size) {
    const float* x     = (const float*)d_in[0];
    const float* w_qkv = (const float*)d_in[1];
    const float* w_out = (const float*)d_in[2];
    float* out = (float*)d_out;

    __half *qkvh, *xh, *wqh, *woh, *atth;
    cudaGetSymbolAddress((void**)&qkvh, g_qkvh);
    cudaGetSymbolAddress((void**)&xh, g_xh);
    cudaGetSymbolAddress((void**)&wqh, g_wqh);
    cudaGetSymbolAddress((void**)&woh, g_woh);
    cudaGetSymbolAddress((void**)&atth, g_atth);

    cudaFuncSetAttribute(gemm_f16_pipe<__half>,
                         cudaFuncAttributeMaxDynamicSharedMemorySize, GSMEM_B);
    cudaFuncSetAttribute(gemm_f16_pipe<float>,
                         cudaFuncAttributeMaxDynamicSharedMemorySize, GSMEM_B);
    cudaFuncSetAttribute(local_attn_f16,
                         cudaFuncAttributeMaxDynamicSharedMemorySize, AT_SMEM);

    // 0) fused conversions
    {
        const int total = X4 + WQ4 + WO4;
        cvt_all<<<(total + 255) / 256, 256>>>((const float4*)x, (const float4*)w_qkv,
                                              (const float4*)w_out,
                                              (uint2*)xh, (uint2*)wqh, (uint2*)woh);
    }

    // 1) QKV: (4096,3072) = x * w_qkv^T -> fp16
    {
        dim3 grid(3 * HID / 128, M_TOT / 256);
        gemm_f16_pipe<__half><<<grid, 512, GSMEM_B>>>(xh, wqh, qkvh, M_TOT, 3 * HID, HID);
    }

    // 2) local attention (fp16 in/out)
    {
        dim3 grid(32, NHEAD, BATCH);
        local_attn_f16<<<grid, 256, AT_SMEM>>>(qkvh, atth);
    }

    // 3) out-proj: (4096,1024) = att * w_out^T -> fp32 output
    {
        dim3 grid(HID / 128, M_TOT / 256);
        gemm_f16_pipe<float><<<grid, 512, GSMEM_B>>>(atth, woh, out, M_TOT, HID, HID);
    }
}